// round 3
// baseline (speedup 1.0000x reference)
#include <cuda_runtime.h>

// Problem constants
#define NS 131072
#define DD 16
#define RR 32
#define OO 10
#define EPSV 1e-8f

#define TPB 128

// Parameter block layout (floats):
//  [r*32 + 0..15]   centers[r][d]
//  [r*32 + 16..31]  k[r][d] = -0.5/sigma^2
//  [1024 + r*204 + row*12 + o]  coeffs[r][row][o], row 0..16 (16=bias), o padded 10->12
#define PBASE_W 1024
#define PTOTAL 7552

__constant__ __align__(16) float gP[PTOTAL];
__device__ __align__(16) float gScratch[PTOTAL];

// ---------------- packed f32x2 helpers (Blackwell) ----------------
__device__ __forceinline__ long long pk2(float a, float b) {
    long long r;
    asm("mov.b64 %0, {%1, %2};" : "=l"(r) : "f"(a), "f"(b));
    return r;
}
__device__ __forceinline__ void unpk2(long long v, float& a, float& b) {
    asm("mov.b64 {%0, %1}, %2;" : "=f"(a), "=f"(b) : "l"(v));
}
__device__ __forceinline__ long long f2fma(long long a, long long b, long long c) {
    long long d;
    asm("fma.rn.f32x2 %0, %1, %2, %3;" : "=l"(d) : "l"(a), "l"(b), "l"(c));
    return d;
}
__device__ __forceinline__ long long f2sub(long long a, long long b) {
    long long d;
    asm("sub.rn.f32x2 %0, %1, %2;" : "=l"(d) : "l"(a), "l"(b));
    return d;
}
__device__ __forceinline__ long long f2mul(long long a, long long b) {
    long long d;
    asm("mul.rn.f32x2 %0, %1, %2;" : "=l"(d) : "l"(a), "l"(b));
    return d;
}
__device__ __forceinline__ long long f2add(long long a, long long b) {
    long long d;
    asm("add.rn.f32x2 %0, %1, %2;" : "=l"(d) : "l"(a), "l"(b));
    return d;
}

// -------- prep: transform params into gScratch (then D2D copy -> gP) --------
__global__ void prep_kernel(const float* __restrict__ centers,
                            const float* __restrict__ sigmas,
                            const float* __restrict__ coeffs) {
    int t = threadIdx.x;
    for (int i = t; i < RR * DD; i += 256) {
        int r = i >> 4, d = i & 15;
        float s = sigmas[i];
        gScratch[r * 32 + d] = centers[i];
        gScratch[r * 32 + 16 + d] = -0.5f / (s * s);
    }
    for (int i = t; i < RR * (DD + 1) * OO; i += 256) {
        int r = i / 170;
        int rem = i - r * 170;
        int row = rem / 10;
        int o = rem - row * 10;
        gScratch[PBASE_W + r * 204 + row * 12 + o] = coeffs[i];
    }
    // zero the o=10,11 padding (never read, but keep deterministic)
    for (int i = t; i < RR * (DD + 1); i += 256) {
        int r = i / 17, row = i % 17;
        gScratch[PBASE_W + r * 204 + row * 12 + 10] = 0.0f;
        gScratch[PBASE_W + r * 204 + row * 12 + 11] = 0.0f;
    }
}

__global__ void __launch_bounds__(TPB, 6)
anfis_kernel(const float* __restrict__ X, float* __restrict__ out) {
    const int n = blockIdx.x * TPB + threadIdx.x;

    // load input row (64B, float4) -> scalars + dimension-pair packs
    float x[16];
    {
        const float4* p = (const float4*)(X + (size_t)n * DD);
        float4 a = p[0], b = p[1], c = p[2], d = p[3];
        x[0] = a.x; x[1] = a.y; x[2] = a.z; x[3] = a.w;
        x[4] = b.x; x[5] = b.y; x[6] = b.z; x[7] = b.w;
        x[8] = c.x; x[9] = c.y; x[10] = c.z; x[11] = c.w;
        x[12] = d.x; x[13] = d.y; x[14] = d.z; x[15] = d.w;
    }
    long long xp[8];
    #pragma unroll
    for (int j = 0; j < 8; j++) xp[j] = pk2(x[2 * j], x[2 * j + 1]);

    long long acc[5];
    #pragma unroll
    for (int j = 0; j < 5; j++) acc[j] = 0LL;
    float ssum = 0.0f;

    #pragma unroll 2
    for (int r = 0; r < RR; r++) {
        // ---- rule strength: packed over (even,odd) dim pairs, from constant ----
        const long long* cp = (const long long*)(gP + r * 32);       // 8 c-pairs
        const long long* kp = (const long long*)(gP + r * 32 + 16);  // 8 k-pairs
        long long ea = 0LL, eb = 0LL;
        #pragma unroll
        for (int j = 0; j < 8; j += 2) {
            long long dfa = f2sub(xp[j], cp[j]);
            ea = f2fma(f2mul(dfa, dfa), kp[j], ea);
            long long dfb = f2sub(xp[j + 1], cp[j + 1]);
            eb = f2fma(f2mul(dfb, dfb), kp[j + 1], eb);
        }
        float e0, e1;
        unpk2(f2add(ea, eb), e0, e1);
        float s = __expf(e0 + e1);
        ssum += s;

        // ---- consequent: t[o-pair] = b[r,o] + sum_d x_d * C[r,d,o] ----
        const float* Crow = gP + PBASE_W + r * 204;
        long long t[5];
        {
            longlong2 bA = *(const longlong2*)(Crow + 192);  // bias o0..o3
            longlong2 bB = *(const longlong2*)(Crow + 196);  // o4..o7
            long long bC = *(const long long*)(Crow + 200);  // o8,o9
            t[0] = bA.x; t[1] = bA.y; t[2] = bB.x; t[3] = bB.y; t[4] = bC;
        }
        #pragma unroll
        for (int d = 0; d < DD; d++) {
            const float* p = Crow + d * 12;
            longlong2 cA = *(const longlong2*)p;        // (o0,o1),(o2,o3)
            longlong2 cB = *(const longlong2*)(p + 4);  // (o4,o5),(o6,o7)
            long long cC = *(const long long*)(p + 8);  // (o8,o9)
            long long xa = pk2(x[d], x[d]);
            t[0] = f2fma(xa, cA.x, t[0]);
            t[1] = f2fma(xa, cA.y, t[1]);
            t[2] = f2fma(xa, cB.x, t[2]);
            t[3] = f2fma(xa, cB.y, t[3]);
            t[4] = f2fma(xa, cC, t[4]);
        }

        // ---- acc += s_r * t ----
        long long sp = pk2(s, s);
        #pragma unroll
        for (int j = 0; j < 5; j++) acc[j] = f2fma(sp, t[j], acc[j]);
    }

    // ---- finalize: normalize, softmax(10), store ----
    float v[10];
    #pragma unroll
    for (int j = 0; j < 5; j++) unpk2(acc[j], v[2 * j], v[2 * j + 1]);

    float inv = __fdividef(1.0f, ssum + EPSV);
    #pragma unroll
    for (int i = 0; i < 10; i++) v[i] *= inv;

    float m = v[0];
    #pragma unroll
    for (int i = 1; i < 10; i++) m = fmaxf(m, v[i]);

    float se = 0.0f;
    #pragma unroll
    for (int i = 0; i < 10; i++) { v[i] = __expf(v[i] - m); se += v[i]; }
    float is = __fdividef(1.0f, se);

    float2* o2 = (float2*)(out + (size_t)n * OO);  // 40B row base -> 8B aligned
    #pragma unroll
    for (int j = 0; j < 5; j++) {
        float2 w; w.x = v[2 * j] * is; w.y = v[2 * j + 1] * is;
        o2[j] = w;
    }
}

extern "C" void kernel_launch(void* const* d_in, const int* in_sizes, int n_in,
                              void* d_out, int out_size) {
    const float* X = (const float*)d_in[0];
    const float* centers = (const float*)d_in[1];
    const float* sigmas = (const float*)d_in[2];
    const float* coeffs = (const float*)d_in[3];
    float* out = (float*)d_out;

    prep_kernel<<<1, 256>>>(centers, sigmas, coeffs);

    void* src = nullptr;
    cudaGetSymbolAddress(&src, gScratch);
    cudaMemcpyToSymbolAsync(gP, src, PTOTAL * sizeof(float), 0,
                            cudaMemcpyDeviceToDevice, 0);

    anfis_kernel<<<NS / TPB, TPB>>>(X, out);
}

// round 5
// speedup vs baseline: 7.9004x; 7.9004x over previous
#include <cuda_runtime.h>

// Problem constants
#define NS 131072
#define DD 16
#define RR 32
#define OO 10
#define EPSV 1e-8f

#define TPB 128   // threads per block
#define SPT 2     // samples per thread
// rows per block = TPB*SPT = 256  -> grid = 512 blocks

// ---------------- packed f32x2 helpers (Blackwell) ----------------
__device__ __forceinline__ long long pk2(float a, float b) {
    long long r;
    asm("mov.b64 %0, {%1, %2};" : "=l"(r) : "f"(a), "f"(b));
    return r;
}
__device__ __forceinline__ void unpk2(long long v, float& a, float& b) {
    asm("mov.b64 {%0, %1}, %2;" : "=f"(a), "=f"(b) : "l"(v));
}
__device__ __forceinline__ long long f2fma(long long a, long long b, long long c) {
    long long d;
    asm("fma.rn.f32x2 %0, %1, %2, %3;" : "=l"(d) : "l"(a), "l"(b), "l"(c));
    return d;
}
__device__ __forceinline__ long long f2sub(long long a, long long b) {
    long long d;
    asm("sub.rn.f32x2 %0, %1, %2;" : "=l"(d) : "l"(a), "l"(b));
    return d;
}
__device__ __forceinline__ long long f2mul(long long a, long long b) {
    long long d;
    asm("mul.rn.f32x2 %0, %1, %2;" : "=l"(d) : "l"(a), "l"(b));
    return d;
}
__device__ __forceinline__ long long f2add(long long a, long long b) {
    long long d;
    asm("add.rn.f32x2 %0, %1, %2;" : "=l"(d) : "l"(a), "l"(b));
    return d;
}

// finalize one sample: scale by 1/(ssum+eps), softmax over 10, store
__device__ __forceinline__ void finish_sample(const long long acc[5], float ssum,
                                              float* __restrict__ outp) {
    float v[10];
    #pragma unroll
    for (int j = 0; j < 5; j++) unpk2(acc[j], v[2 * j], v[2 * j + 1]);

    float inv = __fdividef(1.0f, ssum + EPSV);
    #pragma unroll
    for (int i = 0; i < 10; i++) v[i] *= inv;

    float m = v[0];
    #pragma unroll
    for (int i = 1; i < 10; i++) m = fmaxf(m, v[i]);

    float s = 0.0f;
    #pragma unroll
    for (int i = 0; i < 10; i++) { v[i] = __expf(v[i] - m); s += v[i]; }
    float is = __fdividef(1.0f, s);

    float2* o2 = (float2*)outp;  // row base is 40B -> 8B aligned
    #pragma unroll
    for (int j = 0; j < 5; j++) {
        float2 w; w.x = v[2 * j] * is; w.y = v[2 * j + 1] * is;
        o2[j] = w;
    }
}

__global__ void __launch_bounds__(TPB, 4)
anfis_kernel(const float* __restrict__ X,
             const float* __restrict__ centers,
             const float* __restrict__ sigmas,
             const float* __restrict__ coeffs,
             float* __restrict__ out) {
    // shared parameter caches
    __shared__ __align__(16) long long sC[RR * DD];   // (c,c) packed      4 KB
    __shared__ __align__(16) long long sK[RR * DD];   // (-1/2s^2) packed  4 KB
    __shared__ __align__(16) float sW[RR * 17 * 12];  // coeffs, o padded 10->12, 25.5 KB

    const int tid = threadIdx.x;

    for (int i = tid; i < RR * DD; i += TPB) {
        float c = centers[i];
        float s = sigmas[i];
        float k = -0.5f / (s * s);
        sC[i] = pk2(c, c);
        sK[i] = pk2(k, k);
    }
    for (int i = tid; i < RR * (DD + 1) * OO; i += TPB) {
        int r = i / 170;
        int rem = i - r * 170;
        int row = rem / 10;
        int o = rem - row * 10;
        sW[r * 204 + row * 12 + o] = coeffs[i];
    }
    __syncthreads();

    const int n0 = blockIdx.x * (TPB * SPT) + tid;
    const int n1 = n0 + TPB;

    // load the two input rows (64B each, float4)
    float x0[16], x1[16];
    {
        const float4* p = (const float4*)(X + (size_t)n0 * DD);
        float4 a = p[0], b = p[1], c = p[2], d = p[3];
        x0[0] = a.x; x0[1] = a.y; x0[2] = a.z; x0[3] = a.w;
        x0[4] = b.x; x0[5] = b.y; x0[6] = b.z; x0[7] = b.w;
        x0[8] = c.x; x0[9] = c.y; x0[10] = c.z; x0[11] = c.w;
        x0[12] = d.x; x0[13] = d.y; x0[14] = d.z; x0[15] = d.w;
    }
    {
        const float4* p = (const float4*)(X + (size_t)n1 * DD);
        float4 a = p[0], b = p[1], c = p[2], d = p[3];
        x1[0] = a.x; x1[1] = a.y; x1[2] = a.z; x1[3] = a.w;
        x1[4] = b.x; x1[5] = b.y; x1[6] = b.z; x1[7] = b.w;
        x1[8] = c.x; x1[9] = c.y; x1[10] = c.z; x1[11] = c.w;
        x1[12] = d.x; x1[13] = d.y; x1[14] = d.z; x1[15] = d.w;
    }

    long long acc0[5], acc1[5];
    #pragma unroll
    for (int j = 0; j < 5; j++) { acc0[j] = 0LL; acc1[j] = 0LL; }
    float ssum0 = 0.0f, ssum1 = 0.0f;

    // unroll 2: rule r+1's shared loads + strength chain overlap rule r's
    // consequent FMA stream (R0's unroll-1 serialization was the issue cap)
    #pragma unroll 2
    for (int r = 0; r < RR; r++) {
        // ---- rule strength: e = sum_d -(x-c)^2/(2 s^2), packed (sample0,sample1) ----
        const long long* cr = sC + r * DD;
        const long long* kr = sK + r * DD;
        long long ea = 0LL, eb = 0LL;
        #pragma unroll
        for (int d = 0; d < DD; d += 2) {
            long long xpa = pk2(x0[d], x1[d]);
            long long dfa = f2sub(xpa, cr[d]);
            ea = f2fma(f2mul(dfa, dfa), kr[d], ea);
            long long xpb = pk2(x0[d + 1], x1[d + 1]);
            long long dfb = f2sub(xpb, cr[d + 1]);
            eb = f2fma(f2mul(dfb, dfb), kr[d + 1], eb);
        }
        float e0, e1;
        unpk2(f2add(ea, eb), e0, e1);
        float s0 = __expf(e0);
        float s1 = __expf(e1);
        ssum0 += s0;
        ssum1 += s1;

        // ---- consequent: t[o] = b[r,o] + sum_d x_d * C[r,d,o], 5 packed pairs ----
        const float* Crow = sW + r * 204;
        long long t0[5], t1[5];
        {
            longlong2 bA = *(const longlong2*)(Crow + 192);  // o0..o3 (bias row i=16)
            longlong2 bB = *(const longlong2*)(Crow + 196);  // o4..o7
            long long bC = *(const long long*)(Crow + 200);  // o8,o9
            t0[0] = bA.x; t0[1] = bA.y; t0[2] = bB.x; t0[3] = bB.y; t0[4] = bC;
            t1[0] = bA.x; t1[1] = bA.y; t1[2] = bB.x; t1[3] = bB.y; t1[4] = bC;
        }
        #pragma unroll
        for (int d = 0; d < DD; d++) {
            const float* p = Crow + d * 12;
            longlong2 cA = *(const longlong2*)p;        // (o0,o1),(o2,o3)
            longlong2 cB = *(const longlong2*)(p + 4);  // (o4,o5),(o6,o7)
            long long cC = *(const long long*)(p + 8);  // (o8,o9)
            long long xa = pk2(x0[d], x0[d]);
            long long xb = pk2(x1[d], x1[d]);
            t0[0] = f2fma(xa, cA.x, t0[0]);
            t0[1] = f2fma(xa, cA.y, t0[1]);
            t0[2] = f2fma(xa, cB.x, t0[2]);
            t0[3] = f2fma(xa, cB.y, t0[3]);
            t0[4] = f2fma(xa, cC, t0[4]);
            t1[0] = f2fma(xb, cA.x, t1[0]);
            t1[1] = f2fma(xb, cA.y, t1[1]);
            t1[2] = f2fma(xb, cB.x, t1[2]);
            t1[3] = f2fma(xb, cB.y, t1[3]);
            t1[4] = f2fma(xb, cC, t1[4]);
        }

        // ---- acc += s_r * t (unnormalized; divide by (ssum+eps) at the end) ----
        long long sp0 = pk2(s0, s0);
        long long sp1 = pk2(s1, s1);
        #pragma unroll
        for (int j = 0; j < 5; j++) {
            acc0[j] = f2fma(sp0, t0[j], acc0[j]);
            acc1[j] = f2fma(sp1, t1[j], acc1[j]);
        }
    }

    finish_sample(acc0, ssum0, out + (size_t)n0 * OO);
    finish_sample(acc1, ssum1, out + (size_t)n1 * OO);
}

extern "C" void kernel_launch(void* const* d_in, const int* in_sizes, int n_in,
                              void* d_out, int out_size) {
    const float* X = (const float*)d_in[0];
    const float* centers = (const float*)d_in[1];
    const float* sigmas = (const float*)d_in[2];
    const float* coeffs = (const float*)d_in[3];
    float* out = (float*)d_out;

    const int blocks = NS / (TPB * SPT);  // 512
    anfis_kernel<<<blocks, TPB>>>(X, centers, sigmas, coeffs, out);
}